// round 10
// baseline (speedup 1.0000x reference)
#include <cuda_runtime.h>
#include <cuda_fp16.h>
#include <cstdint>

#define SLEN 2048
#define BSZ  2
#define EMB  1024
#define NH   16
#define DHD  64
#define PFW  16
#define MTOK (SLEN*BSZ)
#define GBK  32              // K per chunk
#define NCHUNK (EMB/GBK)     // 32
#define GBM  128
#define GBN  256
#define STAGES 4
#define ROWB 80              // padded smem row bytes (64 data + 16 pad)
#define SROWS 384            // A 128 rows + B 256 rows
#define STGB (SROWS*ROWB)    // 30720
#define GEMM_SMEM (STAGES*STGB)  // 122880
#define GTHR 512
#define NQKV 3072
#define QPB  16              // queries per warp in attention

// ---------------- scratch (static device arrays; no allocation) -------------
__device__ __align__(16) __half g_xn [MTOK*EMB];        // LN out fp16
__device__ __align__(16) __half g_att[MTOK*EMB];        // attn out fp16
__device__ __align__(16) __half g_wh [4*EMB*EMB];       // Wq|Wk|Wv|Wo fp16, [N][K]
__device__ __align__(16) __half g_qkv[MTOK*NQKV];       // fused QKV output (fp16)
__device__ float g_bias[NQKV];

// ---------------- PTX helpers ------------------------------------------------
__device__ __forceinline__ uint32_t s2u(const void* p) {
    uint32_t a;
    asm("{ .reg .u64 t; cvta.to.shared.u64 t, %1; cvt.u32.u64 %0, t; }" : "=r"(a) : "l"(p));
    return a;
}
__device__ __forceinline__ void cp16(uint32_t dst, const void* src) {
    asm volatile("cp.async.cg.shared.global [%0], [%1], 16;" :: "r"(dst), "l"(src));
}
#define CP_COMMIT() asm volatile("cp.async.commit_group;" ::: "memory")

__device__ __forceinline__ void ldsm4(uint32_t* r, uint32_t addr) {
    asm volatile("ldmatrix.sync.aligned.m8n8.x4.shared.b16 {%0,%1,%2,%3}, [%4];"
        : "=r"(r[0]), "=r"(r[1]), "=r"(r[2]), "=r"(r[3]) : "r"(addr));
}
__device__ __forceinline__ void mma16816(float* d, const uint32_t* a,
                                         uint32_t b0, uint32_t b1) {
    asm volatile("mma.sync.aligned.m16n8k16.row.col.f32.f16.f16.f32 "
        "{%0,%1,%2,%3}, {%4,%5,%6,%7}, {%8,%9}, {%0,%1,%2,%3};"
        : "+f"(d[0]), "+f"(d[1]), "+f"(d[2]), "+f"(d[3])
        : "r"(a[0]), "r"(a[1]), "r"(a[2]), "r"(a[3]), "r"(b0), "r"(b1));
}

// ---------------- merged prep: wprep (blocks 0..4095) + LN (4096..8191)
//                  + bias concat (8192..8203), one launch --------------------
__global__ void __launch_bounds__(256) prep_kernel(
    const float* __restrict__ x,
    const float* __restrict__ gamma,
    const float* __restrict__ beta,
    const float* __restrict__ W0, const float* __restrict__ W1,
    const float* __restrict__ W2, const float* __restrict__ W3,
    const float* __restrict__ bq, const float* __restrict__ bk,
    const float* __restrict__ bv,
    __half* __restrict__ Bh,
    __half* __restrict__ xn,
    float* __restrict__ bqkv)
{
    int bid = blockIdx.x;
    int tid = threadIdx.x;

    if (bid < 4096) {
        // ---- weight transpose + fp16 convert: W[K,N] -> Wh[N,K] ----
        int wsel = bid >> 10;
        int t = bid & 1023;
        int n0 = (t & 31) * 32;
        int k0 = (t >> 5) * 32;
        const float* W = (wsel == 0) ? W0 : (wsel == 1) ? W1
                       : (wsel == 2) ? W2 : W3;
        __half* B = Bh + (size_t)wsel * EMB * EMB;
        __shared__ float tile[32][33];
        int tx = tid & 31;
        int ty = tid >> 5;
        #pragma unroll
        for (int r = ty; r < 32; r += 8)
            tile[r][tx] = W[(size_t)(k0 + r) * EMB + n0 + tx];
        __syncthreads();
        #pragma unroll
        for (int r = ty; r < 32; r += 8)
            B[(size_t)(n0 + r) * EMB + (k0 + tx)] = __float2half(tile[tx][r]);
    } else if (bid < 8192) {
        // ---- LayerNorm row -> fp16 ----
        int row = bid - 4096;
        const float4 xv = ((const float4*)(x + (size_t)row * EMB))[tid];
        float s  = xv.x + xv.y + xv.z + xv.w;
        float s2 = xv.x*xv.x + xv.y*xv.y + xv.z*xv.z + xv.w*xv.w;
        #pragma unroll
        for (int o = 16; o > 0; o >>= 1) {
            s  += __shfl_xor_sync(0xffffffffu, s,  o);
            s2 += __shfl_xor_sync(0xffffffffu, s2, o);
        }
        __shared__ float rs[8], rs2[8];
        __shared__ float mean_s, rstd_s;
        int w = tid >> 5, l = tid & 31;
        if (l == 0) { rs[w] = s; rs2[w] = s2; }
        __syncthreads();
        if (tid == 0) {
            float ts = 0.f, ts2 = 0.f;
            #pragma unroll
            for (int i = 0; i < 8; i++) { ts += rs[i]; ts2 += rs2[i]; }
            float mean = ts * (1.0f / EMB);
            float var  = ts2 * (1.0f / EMB) - mean * mean;
            mean_s = mean;
            rstd_s = rsqrtf(var + 1e-5f);
        }
        __syncthreads();
        float mean = mean_s, r = rstd_s;
        float4 gv = ((const float4*)gamma)[tid];
        float4 bv2 = ((const float4*)beta)[tid];
        __half h[4];
        h[0] = __float2half((xv.x - mean) * r * gv.x + bv2.x);
        h[1] = __float2half((xv.y - mean) * r * gv.y + bv2.y);
        h[2] = __float2half((xv.z - mean) * r * gv.z + bv2.z);
        h[3] = __float2half((xv.w - mean) * r * gv.w + bv2.w);
        *(uint2*)(xn + (size_t)row * EMB + tid * 4) = *(uint2*)h;
    } else {
        // ---- bias concat ----
        int i = (bid - 8192) * 256 + tid;
        if (i < NQKV)
            bqkv[i] = (i < EMB) ? bq[i] : (i < 2*EMB) ? bk[i - EMB] : bv[i - 2*EMB];
    }
}

// ---------------- HMMA fp16 GEMM: C = A @ B^T + bias (+res) ----------------
// A: [M, 1024] fp16.  B: [N, 1024] fp16 ([N][K]).
// CTA tile 128x256, 16 warps, warp tile 32x64, 4-stage cp.async.
template<int OUT_HALF>
__global__ void __launch_bounds__(GTHR, 1) gemm_mma(
    const __half* __restrict__ A,
    const __half* __restrict__ B,
    const float* __restrict__ bias,
    const float* __restrict__ res,
    void* __restrict__ Cv,
    int ldc)
{
    extern __shared__ char smem[];
    uint32_t sb = s2u(smem);
    int tid = threadIdx.x;
    int w = tid >> 5, l = tid & 31;
    int bm = blockIdx.y * GBM;
    int bn = blockIdx.x * GBN;
    int wm = (w & 3) * 32;
    int wn = (w >> 2) * 64;

    // hoisted load addressing: each thread owns 3 (row, 16B-chunk) slots
    int r0 = tid >> 2;           // 0..127
    int ch = tid & 3;
    const __half* p0 = A + (size_t)(bm + r0) * EMB + ch * 8;        // A row r0
    const __half* p1 = B + (size_t)(bn + r0) * EMB + ch * 8;        // B row r0
    const __half* p2 = B + (size_t)(bn + r0 + 128) * EMB + ch * 8;  // B row r0+128
    uint32_t d0 = (uint32_t)r0 * ROWB + ch * 16;
    uint32_t d1 = d0 + 128 * ROWB;
    uint32_t d2 = d0 + 256 * ROWB;

    float acc[2][8][4];
    #pragma unroll
    for (int i = 0; i < 2; i++)
        #pragma unroll
        for (int j = 0; j < 8; j++)
            #pragma unroll
            for (int t = 0; t < 4; t++) acc[i][j][t] = 0.f;

    // prologue: fill STAGES-1 stages
    #pragma unroll
    for (int c = 0; c < STAGES - 1; c++) {
        uint32_t stg = sb + c * STGB;
        cp16(stg + d0, p0); p0 += GBK;
        cp16(stg + d1, p1); p1 += GBK;
        cp16(stg + d2, p2); p2 += GBK;
        CP_COMMIT();
    }

    uint32_t arow = (uint32_t)(wm + (l & 15)) * ROWB + ((l >> 4) << 4);
    uint32_t brow = (uint32_t)(128 + wn + (l & 15)) * ROWB + ((l >> 4) << 4);

    for (int c0 = 0; c0 < NCHUNK; c0 += STAGES) {
        #pragma unroll
        for (int s = 0; s < STAGES; s++) {
            int c = c0 + s;
            asm volatile("cp.async.wait_group %0;" :: "n"(STAGES - 2) : "memory");
            __syncthreads();
            uint32_t stg = sb + (uint32_t)s * STGB;   // compile-time stage offset

            // issue next-stage loads first (overlap with MMA)
            if (c + STAGES - 1 < NCHUNK) {
                uint32_t ds = sb + (uint32_t)(((unsigned)(s + STAGES - 1)) & (STAGES - 1)) * STGB;
                cp16(ds + d0, p0); p0 += GBK;
                cp16(ds + d1, p1); p1 += GBK;
                cp16(ds + d2, p2); p2 += GBK;
            }
            CP_COMMIT();

            uint32_t sA = stg + arow;
            uint32_t sB = stg + brow;

            #pragma unroll
            for (int ks = 0; ks < 2; ks++) {
                uint32_t af[2][4], br[4][4];
                #pragma unroll
                for (int mt = 0; mt < 2; mt++)
                    ldsm4(af[mt], sA + mt * (16 * ROWB) + ks * 32);
                #pragma unroll
                for (int bt = 0; bt < 4; bt++)
                    ldsm4(br[bt], sB + bt * (16 * ROWB) + ks * 32);
                #pragma unroll
                for (int mt = 0; mt < 2; mt++)
                    #pragma unroll
                    for (int bt = 0; bt < 4; bt++) {
                        mma16816(acc[mt][2 * bt],     af[mt], br[bt][0], br[bt][2]);
                        mma16816(acc[mt][2 * bt + 1], af[mt], br[bt][1], br[bt][3]);
                    }
            }
        }
    }

    // epilogue
    int rbase = bm + wm + (l >> 2);
    int cbase = bn + wn + 2 * (l & 3);
    #pragma unroll
    for (int mt = 0; mt < 2; mt++) {
        #pragma unroll
        for (int nt = 0; nt < 8; nt++) {
            int col = cbase + nt * 8;
            float bx = bias[col], by = bias[col + 1];
            int rr0 = rbase + mt * 16;
            int rr1 = rr0 + 8;
            float v0x = acc[mt][nt][0] + bx;
            float v0y = acc[mt][nt][1] + by;
            float v1x = acc[mt][nt][2] + bx;
            float v1y = acc[mt][nt][3] + by;
            if (OUT_HALF) {
                __half* C = (__half*)Cv;
                *(__half2*)(C + (size_t)rr0 * ldc + col) = __floats2half2_rn(v0x, v0y);
                *(__half2*)(C + (size_t)rr1 * ldc + col) = __floats2half2_rn(v1x, v1y);
            } else {
                float* C = (float*)Cv;
                float2 q0 = *(const float2*)(res + (size_t)rr0 * EMB + col);
                float2 q1 = *(const float2*)(res + (size_t)rr1 * EMB + col);
                float2 o0 = {v0x + q0.x, v0y + q0.y};
                float2 o1 = {v1x + q1.x, v1y + q1.y};
                *(float2*)(C + (size_t)rr0 * ldc + col) = o0;
                *(float2*)(C + (size_t)rr1 * ldc + col) = o1;
            }
        }
    }
}

// ---------------- sliding-window attention (fp16 QKV) -> fp16 output --------
// Each warp = one head; processes QPB consecutive queries so the K/V window
// overlaps 15/16 between steps and stays L1-resident.
__global__ void __launch_bounds__(512) attn_kernel(
    const __half* __restrict__ QKV,
    __half* __restrict__ O)
{
    int s0 = blockIdx.x * QPB;
    int b = blockIdx.y;
    int h = threadIdx.x >> 5;
    int lane = threadIdx.x & 31;
    int hoff = h * DHD;

    for (int qi = 0; qi < QPB; qi++) {
        int s = s0 + qi;
        int t = s * BSZ + b;

        const __half2* qp = (const __half2*)(QKV + (size_t)t * NQKV + hoff);
        float2 qv = __half22float2(qp[lane]);

        float sc[PFW];
        #pragma unroll
        for (int p = 0; p < PFW; p++) {
            int sp = s + p - (PFW - 1);
            if (sp < 0) sp += SLEN;
            const __half2* kp = (const __half2*)(QKV + (size_t)(sp * BSZ + b) * NQKV + EMB + hoff);
            float2 kv = __half22float2(kp[lane]);
            float d = qv.x * kv.x + qv.y * kv.y;
            #pragma unroll
            for (int o = 16; o > 0; o >>= 1) d += __shfl_xor_sync(0xffffffffu, d, o);
            sc[p] = d * 0.125f;
        }

        float mx = sc[0];
        #pragma unroll
        for (int p = 1; p < PFW; p++) mx = fmaxf(mx, sc[p]);
        float sum = 0.f;
        #pragma unroll
        for (int p = 0; p < PFW; p++) { sc[p] = __expf(sc[p] - mx); sum += sc[p]; }
        float inv = 1.0f / sum;

        float o0 = 0.f, o1 = 0.f;
        #pragma unroll
        for (int p = 0; p < PFW; p++) {
            int sp = s + p - (PFW - 1);
            if (sp < 0) sp += SLEN;
            const __half2* vp = (const __half2*)(QKV + (size_t)(sp * BSZ + b) * NQKV + 2 * EMB + hoff);
            float2 vv = __half22float2(vp[lane]);
            float wgt = sc[p] * inv;
            o0 += wgt * vv.x;
            o1 += wgt * vv.y;
        }
        __half2* op = (__half2*)(O + (size_t)t * EMB + hoff);
        op[lane] = __floats2half2_rn(o0, o1);
    }
}

// ---------------- launch ----------------------------------------------------
extern "C" void kernel_launch(void* const* d_in, const int* in_sizes, int n_in,
                              void* d_out, int out_size)
{
    const float* x    = (const float*)d_in[0];
    const float* ln_g = (const float*)d_in[1];
    const float* ln_b = (const float*)d_in[2];
    const float* Wq   = (const float*)d_in[3];
    const float* bq   = (const float*)d_in[4];
    const float* Wk   = (const float*)d_in[5];
    const float* bk   = (const float*)d_in[6];
    const float* Wv   = (const float*)d_in[7];
    const float* bv   = (const float*)d_in[8];
    const float* Wo   = (const float*)d_in[9];
    const float* bo   = (const float*)d_in[10];
    float* out = (float*)d_out;

    __half *xn, *att, *wh, *qkv;
    float *bias;
    cudaGetSymbolAddress((void**)&xn,   g_xn);
    cudaGetSymbolAddress((void**)&att,  g_att);
    cudaGetSymbolAddress((void**)&wh,   g_wh);
    cudaGetSymbolAddress((void**)&qkv,  g_qkv);
    cudaGetSymbolAddress((void**)&bias, g_bias);

    cudaFuncSetAttribute(gemm_mma<1>, cudaFuncAttributeMaxDynamicSharedMemorySize, GEMM_SMEM);
    cudaFuncSetAttribute(gemm_mma<0>, cudaFuncAttributeMaxDynamicSharedMemorySize, GEMM_SMEM);

    // one merged prep launch: weight transpose + LN + bias concat
    prep_kernel<<<8204, 256>>>(x, ln_g, ln_b, Wq, Wk, Wv, Wo,
                               bq, bk, bv, wh, xn, bias);

    // fused QKV: C[4096, 3072] fp16
    gemm_mma<1><<<dim3(NQKV / GBN, MTOK / GBM), GTHR, GEMM_SMEM>>>(
        xn, wh, bias, nullptr, qkv, NQKV);

    attn_kernel<<<dim3(SLEN / QPB, BSZ), 512>>>(qkv, att);

    // output projection + residual (fp32 out)
    gemm_mma<0><<<dim3(EMB / GBN, MTOK / GBM), GTHR, GEMM_SMEM>>>(
        att, wh + (size_t)3 * EMB * EMB, bo, x, out, EMB);
}

// round 11
// speedup vs baseline: 1.0141x; 1.0141x over previous
#include <cuda_runtime.h>
#include <cuda_fp16.h>
#include <cstdint>

#define SLEN 2048
#define BSZ  2
#define EMB  1024
#define NH   16
#define DHD  64
#define PFW  16
#define MTOK (SLEN*BSZ)
#define GBK  32              // K per chunk
#define NCHUNK (EMB/GBK)     // 32
#define GBM  128
#define GBN  256
#define STAGES 4
#define ROWB 80              // padded smem row bytes (64 data + 16 pad)
#define SROWS 384            // A 128 rows + B 256 rows
#define STGB (SROWS*ROWB)    // 30720
#define GEMM_SMEM (STAGES*STGB)  // 122880
#define GTHR 512
#define NQKV 3072
#define QPB  16              // queries per warp in attention

// ---------------- scratch (static device arrays; no allocation) -------------
__device__ __align__(16) __half g_xn [MTOK*EMB];        // LN out fp16
__device__ __align__(16) __half g_att[MTOK*EMB];        // attn out fp16
__device__ __align__(16) __half g_wh [4*EMB*EMB];       // Wq|Wk|Wv|Wo fp16, [N][K]
__device__ __align__(16) __half g_qkv[MTOK*NQKV];       // fused QKV output (fp16)
__device__ float g_bias[NQKV];

// ---------------- PTX helpers ------------------------------------------------
__device__ __forceinline__ uint32_t s2u(const void* p) {
    uint32_t a;
    asm("{ .reg .u64 t; cvta.to.shared.u64 t, %1; cvt.u32.u64 %0, t; }" : "=r"(a) : "l"(p));
    return a;
}
__device__ __forceinline__ void cp16(uint32_t dst, const void* src) {
    asm volatile("cp.async.cg.shared.global [%0], [%1], 16;" :: "r"(dst), "l"(src));
}
#define CP_COMMIT() asm volatile("cp.async.commit_group;" ::: "memory")

__device__ __forceinline__ void ldsm4(uint32_t* r, uint32_t addr) {
    asm volatile("ldmatrix.sync.aligned.m8n8.x4.shared.b16 {%0,%1,%2,%3}, [%4];"
        : "=r"(r[0]), "=r"(r[1]), "=r"(r[2]), "=r"(r[3]) : "r"(addr));
}
__device__ __forceinline__ void mma16816(float* d, const uint32_t* a,
                                         uint32_t b0, uint32_t b1) {
    asm volatile("mma.sync.aligned.m16n8k16.row.col.f32.f16.f16.f32 "
        "{%0,%1,%2,%3}, {%4,%5,%6,%7}, {%8,%9}, {%0,%1,%2,%3};"
        : "+f"(d[0]), "+f"(d[1]), "+f"(d[2]), "+f"(d[3])
        : "r"(a[0]), "r"(a[1]), "r"(a[2]), "r"(a[3]), "r"(b0), "r"(b1));
}

// ---------------- merged prep: wprep (blocks 0..4095) + LN (4096..8191)
//                  + bias concat (8192..8203), one launch --------------------
__global__ void __launch_bounds__(256) prep_kernel(
    const float* __restrict__ x,
    const float* __restrict__ gamma,
    const float* __restrict__ beta,
    const float* __restrict__ W0, const float* __restrict__ W1,
    const float* __restrict__ W2, const float* __restrict__ W3,
    const float* __restrict__ bq, const float* __restrict__ bk,
    const float* __restrict__ bv,
    __half* __restrict__ Bh,
    __half* __restrict__ xn,
    float* __restrict__ bqkv)
{
    int bid = blockIdx.x;
    int tid = threadIdx.x;

    if (bid < 4096) {
        // ---- weight transpose + fp16 convert: W[K,N] -> Wh[N,K] ----
        int wsel = bid >> 10;
        int t = bid & 1023;
        int n0 = (t & 31) * 32;
        int k0 = (t >> 5) * 32;
        const float* W = (wsel == 0) ? W0 : (wsel == 1) ? W1
                       : (wsel == 2) ? W2 : W3;
        __half* B = Bh + (size_t)wsel * EMB * EMB;
        __shared__ float tile[32][33];
        int tx = tid & 31;
        int ty = tid >> 5;
        #pragma unroll
        for (int r = ty; r < 32; r += 8)
            tile[r][tx] = W[(size_t)(k0 + r) * EMB + n0 + tx];
        __syncthreads();
        #pragma unroll
        for (int r = ty; r < 32; r += 8)
            B[(size_t)(n0 + r) * EMB + (k0 + tx)] = __float2half(tile[tx][r]);
    } else if (bid < 8192) {
        // ---- LayerNorm row -> fp16 ----
        int row = bid - 4096;
        const float4 xv = ((const float4*)(x + (size_t)row * EMB))[tid];
        float s  = xv.x + xv.y + xv.z + xv.w;
        float s2 = xv.x*xv.x + xv.y*xv.y + xv.z*xv.z + xv.w*xv.w;
        #pragma unroll
        for (int o = 16; o > 0; o >>= 1) {
            s  += __shfl_xor_sync(0xffffffffu, s,  o);
            s2 += __shfl_xor_sync(0xffffffffu, s2, o);
        }
        __shared__ float rs[8], rs2[8];
        __shared__ float mean_s, rstd_s;
        int w = tid >> 5, l = tid & 31;
        if (l == 0) { rs[w] = s; rs2[w] = s2; }
        __syncthreads();
        if (tid == 0) {
            float ts = 0.f, ts2 = 0.f;
            #pragma unroll
            for (int i = 0; i < 8; i++) { ts += rs[i]; ts2 += rs2[i]; }
            float mean = ts * (1.0f / EMB);
            float var  = ts2 * (1.0f / EMB) - mean * mean;
            mean_s = mean;
            rstd_s = rsqrtf(var + 1e-5f);
        }
        __syncthreads();
        float mean = mean_s, r = rstd_s;
        float4 gv = ((const float4*)gamma)[tid];
        float4 bv2 = ((const float4*)beta)[tid];
        __half h[4];
        h[0] = __float2half((xv.x - mean) * r * gv.x + bv2.x);
        h[1] = __float2half((xv.y - mean) * r * gv.y + bv2.y);
        h[2] = __float2half((xv.z - mean) * r * gv.z + bv2.z);
        h[3] = __float2half((xv.w - mean) * r * gv.w + bv2.w);
        *(uint2*)(xn + (size_t)row * EMB + tid * 4) = *(uint2*)h;
    } else {
        // ---- bias concat ----
        int i = (bid - 8192) * 256 + tid;
        if (i < NQKV)
            bqkv[i] = (i < EMB) ? bq[i] : (i < 2*EMB) ? bk[i - EMB] : bv[i - 2*EMB];
    }
}

// ---------------- HMMA fp16 GEMM: C = A @ B^T + bias (+res) ----------------
// A: [M, 1024] fp16.  B: [N, 1024] fp16 ([N][K]).
// CTA tile 128x256, 16 warps, warp tile 32x64, 4-stage cp.async.
template<int OUT_HALF>
__global__ void __launch_bounds__(GTHR, 1) gemm_mma(
    const __half* __restrict__ A,
    const __half* __restrict__ B,
    const float* __restrict__ bias,
    const float* __restrict__ res,
    void* __restrict__ Cv,
    int ldc)
{
    extern __shared__ char smem[];
    uint32_t sb = s2u(smem);
    int tid = threadIdx.x;
    int w = tid >> 5, l = tid & 31;
    int bm = blockIdx.y * GBM;
    int bn = blockIdx.x * GBN;
    int wm = (w & 3) * 32;
    int wn = (w >> 2) * 64;

    // hoisted load addressing: each thread owns 3 (row, 16B-chunk) slots
    int r0 = tid >> 2;           // 0..127
    int ch = tid & 3;
    const __half* p0 = A + (size_t)(bm + r0) * EMB + ch * 8;        // A row r0
    const __half* p1 = B + (size_t)(bn + r0) * EMB + ch * 8;        // B row r0
    const __half* p2 = B + (size_t)(bn + r0 + 128) * EMB + ch * 8;  // B row r0+128
    uint32_t d0 = (uint32_t)r0 * ROWB + ch * 16;
    uint32_t d1 = d0 + 128 * ROWB;
    uint32_t d2 = d0 + 256 * ROWB;

    float acc[2][8][4];
    #pragma unroll
    for (int i = 0; i < 2; i++)
        #pragma unroll
        for (int j = 0; j < 8; j++)
            #pragma unroll
            for (int t = 0; t < 4; t++) acc[i][j][t] = 0.f;

    // prologue: fill STAGES-1 stages
    #pragma unroll
    for (int c = 0; c < STAGES - 1; c++) {
        uint32_t stg = sb + c * STGB;
        cp16(stg + d0, p0); p0 += GBK;
        cp16(stg + d1, p1); p1 += GBK;
        cp16(stg + d2, p2); p2 += GBK;
        CP_COMMIT();
    }

    uint32_t arow = (uint32_t)(wm + (l & 15)) * ROWB + ((l >> 4) << 4);
    uint32_t brow = (uint32_t)(128 + wn + (l & 15)) * ROWB + ((l >> 4) << 4);

    for (int c0 = 0; c0 < NCHUNK; c0 += STAGES) {
        #pragma unroll
        for (int s = 0; s < STAGES; s++) {
            int c = c0 + s;
            asm volatile("cp.async.wait_group %0;" :: "n"(STAGES - 2) : "memory");
            __syncthreads();
            uint32_t stg = sb + (uint32_t)s * STGB;   // compile-time stage offset

            // issue next-stage loads first (overlap with MMA)
            if (c + STAGES - 1 < NCHUNK) {
                uint32_t ds = sb + (uint32_t)(((unsigned)(s + STAGES - 1)) & (STAGES - 1)) * STGB;
                cp16(ds + d0, p0); p0 += GBK;
                cp16(ds + d1, p1); p1 += GBK;
                cp16(ds + d2, p2); p2 += GBK;
            }
            CP_COMMIT();

            uint32_t sA = stg + arow;
            uint32_t sB = stg + brow;

            #pragma unroll
            for (int ks = 0; ks < 2; ks++) {
                uint32_t af[2][4], br[4][4];
                #pragma unroll
                for (int mt = 0; mt < 2; mt++)
                    ldsm4(af[mt], sA + mt * (16 * ROWB) + ks * 32);
                #pragma unroll
                for (int bt = 0; bt < 4; bt++)
                    ldsm4(br[bt], sB + bt * (16 * ROWB) + ks * 32);
                #pragma unroll
                for (int mt = 0; mt < 2; mt++)
                    #pragma unroll
                    for (int bt = 0; bt < 4; bt++) {
                        mma16816(acc[mt][2 * bt],     af[mt], br[bt][0], br[bt][2]);
                        mma16816(acc[mt][2 * bt + 1], af[mt], br[bt][1], br[bt][3]);
                    }
            }
        }
    }

    // epilogue
    int rbase = bm + wm + (l >> 2);
    int cbase = bn + wn + 2 * (l & 3);
    #pragma unroll
    for (int mt = 0; mt < 2; mt++) {
        #pragma unroll
        for (int nt = 0; nt < 8; nt++) {
            int col = cbase + nt * 8;
            float bx = bias[col], by = bias[col + 1];
            int rr0 = rbase + mt * 16;
            int rr1 = rr0 + 8;
            float v0x = acc[mt][nt][0] + bx;
            float v0y = acc[mt][nt][1] + by;
            float v1x = acc[mt][nt][2] + bx;
            float v1y = acc[mt][nt][3] + by;
            if (OUT_HALF) {
                __half* C = (__half*)Cv;
                *(__half2*)(C + (size_t)rr0 * ldc + col) = __floats2half2_rn(v0x, v0y);
                *(__half2*)(C + (size_t)rr1 * ldc + col) = __floats2half2_rn(v1x, v1y);
            } else {
                float* C = (float*)Cv;
                float2 q0 = *(const float2*)(res + (size_t)rr0 * EMB + col);
                float2 q1 = *(const float2*)(res + (size_t)rr1 * EMB + col);
                float2 o0 = {v0x + q0.x, v0y + q0.y};
                float2 o1 = {v1x + q1.x, v1y + q1.y};
                *(float2*)(C + (size_t)rr0 * ldc + col) = o0;
                *(float2*)(C + (size_t)rr1 * ldc + col) = o1;
            }
        }
    }
}

// ---------------- sliding-window attention: register-ring K/V reuse ---------
// Warp = one head, 16 consecutive queries. 16-row K/V window lives in
// registers (slot = row & 15 -> compile-time after full unroll, since
// s0 % 16 == 0). Each query loads only ONE new K row + V row slice.
__global__ void __launch_bounds__(512) attn_kernel(
    const __half* __restrict__ QKV,
    __half* __restrict__ O)
{
    int s0 = blockIdx.x * QPB;
    int b = blockIdx.y;
    int h = threadIdx.x >> 5;
    int lane = threadIdx.x & 31;
    int hoff = h * DHD;

    float2 kreg[16], vreg[16];

    // init window: rows s0-15 .. s0  ->  slot (row & 15)
    #pragma unroll
    for (int i = 0; i <= 15; i++) {
        int r = s0 - 15 + i;
        int rw = (r < 0) ? r + SLEN : r;
        const __half2* kp = (const __half2*)(QKV + (size_t)(rw * BSZ + b) * NQKV + EMB + hoff);
        const __half2* vp = (const __half2*)(QKV + (size_t)(rw * BSZ + b) * NQKV + 2 * EMB + hoff);
        int slot = (i + 1) & 15;   // == (s0-15+i) & 15 since s0 % 16 == 0
        kreg[slot] = __half22float2(kp[lane]);
        vreg[slot] = __half22float2(vp[lane]);
    }

    #pragma unroll
    for (int qi = 0; qi < QPB; qi++) {
        int s = s0 + qi;
        int t = s * BSZ + b;
        float2 qv = __half22float2(
            ((const __half2*)(QKV + (size_t)t * NQKV + hoff))[lane]);

        float sc[PFW];
        #pragma unroll
        for (int p = 0; p < PFW; p++) {
            int slot = (qi + p + 1) & 15;   // == (s-15+p) & 15
            float d = qv.x * kreg[slot].x + qv.y * kreg[slot].y;
            #pragma unroll
            for (int o = 16; o > 0; o >>= 1) d += __shfl_xor_sync(0xffffffffu, d, o);
            sc[p] = d * 0.125f;
        }

        float mx = sc[0];
        #pragma unroll
        for (int p = 1; p < PFW; p++) mx = fmaxf(mx, sc[p]);
        float sum = 0.f;
        #pragma unroll
        for (int p = 0; p < PFW; p++) { sc[p] = __expf(sc[p] - mx); sum += sc[p]; }
        float inv = 1.0f / sum;

        float o0 = 0.f, o1 = 0.f;
        #pragma unroll
        for (int p = 0; p < PFW; p++) {
            int slot = (qi + p + 1) & 15;
            float wgt = sc[p] * inv;
            o0 += wgt * vreg[slot].x;
            o1 += wgt * vreg[slot].y;
        }
        __half2* op = (__half2*)(O + (size_t)t * EMB + hoff);
        op[lane] = __floats2half2_rn(o0, o1);

        // slide window: row s+1 replaces oldest row (s-15); same slot.
        if (qi < QPB - 1) {
            int r = s + 1;                 // <= s0+15 < SLEN, no wrap
            int slot = (qi + 1) & 15;      // == r & 15
            const __half2* kp = (const __half2*)(QKV + (size_t)(r * BSZ + b) * NQKV + EMB + hoff);
            const __half2* vp = (const __half2*)(QKV + (size_t)(r * BSZ + b) * NQKV + 2 * EMB + hoff);
            kreg[slot] = __half22float2(kp[lane]);
            vreg[slot] = __half22float2(vp[lane]);
        }
    }
}

// ---------------- launch ----------------------------------------------------
extern "C" void kernel_launch(void* const* d_in, const int* in_sizes, int n_in,
                              void* d_out, int out_size)
{
    const float* x    = (const float*)d_in[0];
    const float* ln_g = (const float*)d_in[1];
    const float* ln_b = (const float*)d_in[2];
    const float* Wq   = (const float*)d_in[3];
    const float* bq   = (const float*)d_in[4];
    const float* Wk   = (const float*)d_in[5];
    const float* bk   = (const float*)d_in[6];
    const float* Wv   = (const float*)d_in[7];
    const float* bv   = (const float*)d_in[8];
    const float* Wo   = (const float*)d_in[9];
    const float* bo   = (const float*)d_in[10];
    float* out = (float*)d_out;

    __half *xn, *att, *wh, *qkv;
    float *bias;
    cudaGetSymbolAddress((void**)&xn,   g_xn);
    cudaGetSymbolAddress((void**)&att,  g_att);
    cudaGetSymbolAddress((void**)&wh,   g_wh);
    cudaGetSymbolAddress((void**)&qkv,  g_qkv);
    cudaGetSymbolAddress((void**)&bias, g_bias);

    cudaFuncSetAttribute(gemm_mma<1>, cudaFuncAttributeMaxDynamicSharedMemorySize, GEMM_SMEM);
    cudaFuncSetAttribute(gemm_mma<0>, cudaFuncAttributeMaxDynamicSharedMemorySize, GEMM_SMEM);

    // one merged prep launch: weight transpose + LN + bias concat
    prep_kernel<<<8204, 256>>>(x, ln_g, ln_b, Wq, Wk, Wv, Wo,
                               bq, bk, bv, wh, xn, bias);

    // fused QKV: C[4096, 3072] fp16
    gemm_mma<1><<<dim3(NQKV / GBN, MTOK / GBM), GTHR, GEMM_SMEM>>>(
        xn, wh, bias, nullptr, qkv, NQKV);

    attn_kernel<<<dim3(SLEN / QPB, BSZ), 512>>>(qkv, att);

    // output projection + residual (fp32 out)
    gemm_mma<0><<<dim3(EMB / GBN, MTOK / GBM), GTHR, GEMM_SMEM>>>(
        att, wh + (size_t)3 * EMB * EMB, bo, x, out, EMB);
}

// round 13
// speedup vs baseline: 1.1067x; 1.0913x over previous
#include <cuda_runtime.h>
#include <cuda_fp16.h>
#include <cstdint>

#define SLEN 2048
#define BSZ  2
#define EMB  1024
#define NH   16
#define DHD  64
#define PFW  16
#define MTOK (SLEN*BSZ)
#define GBK  32              // K per chunk
#define NCHUNK (EMB/GBK)     // 32
#define GBM  128
#define GBN  256
#define STAGES 4
#define ROWB 80              // padded smem row bytes (64 data + 16 pad)
#define SROWS 384            // A 128 rows + B 256 rows
#define STGB (SROWS*ROWB)    // 30720
#define GEMM_SMEM (STAGES*STGB)  // 122880
#define GTHR 512
#define NQKV 3072
#define VROWB 80             // V^T smem row: 32 p * 2B + 16 pad
#define VT_BYTES (64*VROWB)  // 5120 per warp
#define ATTN_SMEM (16*VT_BYTES) // 81920

// ---------------- scratch (static device arrays; no allocation) -------------
__device__ __align__(16) __half g_xn [MTOK*EMB];        // LN out fp16
__device__ __align__(16) __half g_att[MTOK*EMB];        // attn out fp16
__device__ __align__(16) __half g_wh [4*EMB*EMB];       // Wq|Wk|Wv|Wo fp16, [N][K]
__device__ __align__(16) __half g_qkv[MTOK*NQKV];       // fused QKV output (fp16)
__device__ float g_bias[NQKV];

// ---------------- PTX helpers ------------------------------------------------
__device__ __forceinline__ uint32_t s2u(const void* p) {
    uint32_t a;
    asm("{ .reg .u64 t; cvta.to.shared.u64 t, %1; cvt.u32.u64 %0, t; }" : "=r"(a) : "l"(p));
    return a;
}
__device__ __forceinline__ void cp16(uint32_t dst, const void* src) {
    asm volatile("cp.async.cg.shared.global [%0], [%1], 16;" :: "r"(dst), "l"(src));
}
#define CP_COMMIT() asm volatile("cp.async.commit_group;" ::: "memory")

__device__ __forceinline__ void ldsm4(uint32_t* r, uint32_t addr) {
    asm volatile("ldmatrix.sync.aligned.m8n8.x4.shared.b16 {%0,%1,%2,%3}, [%4];"
        : "=r"(r[0]), "=r"(r[1]), "=r"(r[2]), "=r"(r[3]) : "r"(addr));
}
__device__ __forceinline__ void mma16816(float* d, const uint32_t* a,
                                         uint32_t b0, uint32_t b1) {
    asm volatile("mma.sync.aligned.m16n8k16.row.col.f32.f16.f16.f32 "
        "{%0,%1,%2,%3}, {%4,%5,%6,%7}, {%8,%9}, {%0,%1,%2,%3};"
        : "+f"(d[0]), "+f"(d[1]), "+f"(d[2]), "+f"(d[3])
        : "r"(a[0]), "r"(a[1]), "r"(a[2]), "r"(a[3]), "r"(b0), "r"(b1));
}

// ---------------- merged prep: wprep (blocks 0..4095) + LN (4096..8191)
//                  + bias concat (8192..8203), one launch --------------------
__global__ void __launch_bounds__(256) prep_kernel(
    const float* __restrict__ x,
    const float* __restrict__ gamma,
    const float* __restrict__ beta,
    const float* __restrict__ W0, const float* __restrict__ W1,
    const float* __restrict__ W2, const float* __restrict__ W3,
    const float* __restrict__ bq, const float* __restrict__ bk,
    const float* __restrict__ bv,
    __half* __restrict__ Bh,
    __half* __restrict__ xn,
    float* __restrict__ bqkv)
{
    int bid = blockIdx.x;
    int tid = threadIdx.x;

    if (bid < 4096) {
        int wsel = bid >> 10;
        int t = bid & 1023;
        int n0 = (t & 31) * 32;
        int k0 = (t >> 5) * 32;
        const float* W = (wsel == 0) ? W0 : (wsel == 1) ? W1
                       : (wsel == 2) ? W2 : W3;
        __half* B = Bh + (size_t)wsel * EMB * EMB;
        __shared__ float tile[32][33];
        int tx = tid & 31;
        int ty = tid >> 5;
        #pragma unroll
        for (int r = ty; r < 32; r += 8)
            tile[r][tx] = W[(size_t)(k0 + r) * EMB + n0 + tx];
        __syncthreads();
        #pragma unroll
        for (int r = ty; r < 32; r += 8)
            B[(size_t)(n0 + r) * EMB + (k0 + tx)] = __float2half(tile[tx][r]);
    } else if (bid < 8192) {
        int row = bid - 4096;
        const float4 xv = ((const float4*)(x + (size_t)row * EMB))[tid];
        float s  = xv.x + xv.y + xv.z + xv.w;
        float s2 = xv.x*xv.x + xv.y*xv.y + xv.z*xv.z + xv.w*xv.w;
        #pragma unroll
        for (int o = 16; o > 0; o >>= 1) {
            s  += __shfl_xor_sync(0xffffffffu, s,  o);
            s2 += __shfl_xor_sync(0xffffffffu, s2, o);
        }
        __shared__ float rs[8], rs2[8];
        __shared__ float mean_s, rstd_s;
        int w = tid >> 5, l = tid & 31;
        if (l == 0) { rs[w] = s; rs2[w] = s2; }
        __syncthreads();
        if (tid == 0) {
            float ts = 0.f, ts2 = 0.f;
            #pragma unroll
            for (int i = 0; i < 8; i++) { ts += rs[i]; ts2 += rs2[i]; }
            float mean = ts * (1.0f / EMB);
            float var  = ts2 * (1.0f / EMB) - mean * mean;
            mean_s = mean;
            rstd_s = rsqrtf(var + 1e-5f);
        }
        __syncthreads();
        float mean = mean_s, r = rstd_s;
        float4 gv = ((const float4*)gamma)[tid];
        float4 bv2 = ((const float4*)beta)[tid];
        __half h[4];
        h[0] = __float2half((xv.x - mean) * r * gv.x + bv2.x);
        h[1] = __float2half((xv.y - mean) * r * gv.y + bv2.y);
        h[2] = __float2half((xv.z - mean) * r * gv.z + bv2.z);
        h[3] = __float2half((xv.w - mean) * r * gv.w + bv2.w);
        *(uint2*)(xn + (size_t)row * EMB + tid * 4) = *(uint2*)h;
    } else {
        int i = (bid - 8192) * 256 + tid;
        if (i < NQKV)
            bqkv[i] = (i < EMB) ? bq[i] : (i < 2*EMB) ? bk[i - EMB] : bv[i - 2*EMB];
    }
}

// ---------------- HMMA fp16 GEMM: C = A @ B^T + bias (+res) ----------------
template<int OUT_HALF>
__global__ void __launch_bounds__(GTHR, 1) gemm_mma(
    const __half* __restrict__ A,
    const __half* __restrict__ B,
    const float* __restrict__ bias,
    const float* __restrict__ res,
    void* __restrict__ Cv,
    int ldc)
{
    extern __shared__ char smem[];
    uint32_t sb = s2u(smem);
    int tid = threadIdx.x;
    int w = tid >> 5, l = tid & 31;
    int bm = blockIdx.y * GBM;
    int bn = blockIdx.x * GBN;
    int wm = (w & 3) * 32;
    int wn = (w >> 2) * 64;

    int r0 = tid >> 2;
    int ch = tid & 3;
    const __half* p0 = A + (size_t)(bm + r0) * EMB + ch * 8;
    const __half* p1 = B + (size_t)(bn + r0) * EMB + ch * 8;
    const __half* p2 = B + (size_t)(bn + r0 + 128) * EMB + ch * 8;
    uint32_t d0 = (uint32_t)r0 * ROWB + ch * 16;
    uint32_t d1 = d0 + 128 * ROWB;
    uint32_t d2 = d0 + 256 * ROWB;

    float acc[2][8][4];
    #pragma unroll
    for (int i = 0; i < 2; i++)
        #pragma unroll
        for (int j = 0; j < 8; j++)
            #pragma unroll
            for (int t = 0; t < 4; t++) acc[i][j][t] = 0.f;

    #pragma unroll
    for (int c = 0; c < STAGES - 1; c++) {
        uint32_t stg = sb + c * STGB;
        cp16(stg + d0, p0); p0 += GBK;
        cp16(stg + d1, p1); p1 += GBK;
        cp16(stg + d2, p2); p2 += GBK;
        CP_COMMIT();
    }

    uint32_t arow = (uint32_t)(wm + (l & 15)) * ROWB + ((l >> 4) << 4);
    uint32_t brow = (uint32_t)(128 + wn + (l & 15)) * ROWB + ((l >> 4) << 4);

    for (int c0 = 0; c0 < NCHUNK; c0 += STAGES) {
        #pragma unroll
        for (int s = 0; s < STAGES; s++) {
            int c = c0 + s;
            asm volatile("cp.async.wait_group %0;" :: "n"(STAGES - 2) : "memory");
            __syncthreads();
            uint32_t stg = sb + (uint32_t)s * STGB;

            if (c + STAGES - 1 < NCHUNK) {
                uint32_t ds = sb + (uint32_t)(((unsigned)(s + STAGES - 1)) & (STAGES - 1)) * STGB;
                cp16(ds + d0, p0); p0 += GBK;
                cp16(ds + d1, p1); p1 += GBK;
                cp16(ds + d2, p2); p2 += GBK;
            }
            CP_COMMIT();

            uint32_t sA = stg + arow;
            uint32_t sB = stg + brow;

            #pragma unroll
            for (int ks = 0; ks < 2; ks++) {
                uint32_t af[2][4], br[4][4];
                #pragma unroll
                for (int mt = 0; mt < 2; mt++)
                    ldsm4(af[mt], sA + mt * (16 * ROWB) + ks * 32);
                #pragma unroll
                for (int bt = 0; bt < 4; bt++)
                    ldsm4(br[bt], sB + bt * (16 * ROWB) + ks * 32);
                #pragma unroll
                for (int mt = 0; mt < 2; mt++)
                    #pragma unroll
                    for (int bt = 0; bt < 4; bt++) {
                        mma16816(acc[mt][2 * bt],     af[mt], br[bt][0], br[bt][2]);
                        mma16816(acc[mt][2 * bt + 1], af[mt], br[bt][1], br[bt][3]);
                    }
            }
        }
    }

    int rbase = bm + wm + (l >> 2);
    int cbase = bn + wn + 2 * (l & 3);
    #pragma unroll
    for (int mt = 0; mt < 2; mt++) {
        #pragma unroll
        for (int nt = 0; nt < 8; nt++) {
            int col = cbase + nt * 8;
            float bx = bias[col], by = bias[col + 1];
            int rr0 = rbase + mt * 16;
            int rr1 = rr0 + 8;
            float v0x = acc[mt][nt][0] + bx;
            float v0y = acc[mt][nt][1] + by;
            float v1x = acc[mt][nt][2] + bx;
            float v1y = acc[mt][nt][3] + by;
            if (OUT_HALF) {
                __half* C = (__half*)Cv;
                *(__half2*)(C + (size_t)rr0 * ldc + col) = __floats2half2_rn(v0x, v0y);
                *(__half2*)(C + (size_t)rr1 * ldc + col) = __floats2half2_rn(v1x, v1y);
            } else {
                float* C = (float*)Cv;
                float2 q0 = *(const float2*)(res + (size_t)rr0 * EMB + col);
                float2 q1 = *(const float2*)(res + (size_t)rr1 * EMB + col);
                float2 o0 = {v0x + q0.x, v0y + q0.y};
                float2 o1 = {v1x + q1.x, v1y + q1.y};
                *(float2*)(C + (size_t)rr0 * ldc + col) = o0;
                *(float2*)(C + (size_t)rr1 * ldc + col) = o1;
            }
        }
    }
}

// ---------------- tensor-core sliding-window attention ----------------------
// One warp = (16-query block, head, b). Scores S[16x32] = Q(16x64) @ K^T,
// cols j=0..31 map to absolute rows s0-16+j; query qi valid band j in
// [qi+1, qi+16]. Masked softmax (rows live in 4 lanes -> 2 shfls), P kept
// in registers (C-frag == A-frag layout), O = P(16x32) @ V(32x64) with V
// staged transposed in per-warp smem (ldsm4 pattern identical to GEMM).
__global__ void __launch_bounds__(512) attn_kernel(
    const __half* __restrict__ QKV,
    __half* __restrict__ O)
{
    extern __shared__ char smem[];
    int w = threadIdx.x >> 5, l = threadIdx.x & 31;
    char* vbase = smem + w * VT_BYTES;
    uint32_t vtu = s2u(vbase);
    int s0 = blockIdx.x * 16;
    int b = blockIdx.y;
    int hoff = w * DHD;          // warp = head
    int m0 = l >> 2;             // owned rows: m0 and m0+8
    int kq = (l & 3) * 2;

    // ---- stage V^T into per-warp smem: lane j loads V row r_j (64 halves =
    //      32 half2), scatters into all 64 d-rows of the transposed tile ----
    {
        int j = l;
        int r = s0 - 16 + j; if (r < 0) r += SLEN;
        const __half2* vp = (const __half2*)(QKV + (size_t)(r * BSZ + b) * NQKV + 2 * EMB + hoff);
        #pragma unroll
        for (int i = 0; i < 32; i++) {   // FIX: full DHD=64 (was 16 -> NaN)
            __half2 v = vp[i];
            *(__half*)(vbase + (2 * i)     * VROWB + j * 2) = __low2half(v);
            *(__half*)(vbase + (2 * i + 1) * VROWB + j * 2) = __high2half(v);
        }
    }

    // ---- Q A-fragments (direct gmem loads) ----
    const __half* Qb  = QKV + (size_t)((s0 + m0)     * BSZ + b) * NQKV + hoff;
    const __half* Qb8 = QKV + (size_t)((s0 + m0 + 8) * BSZ + b) * NQKV + hoff;
    uint32_t aq[4][4];
    #pragma unroll
    for (int kt = 0; kt < 4; kt++) {
        aq[kt][0] = *(const uint32_t*)(Qb  + kt * 16 + kq);
        aq[kt][1] = *(const uint32_t*)(Qb8 + kt * 16 + kq);
        aq[kt][2] = *(const uint32_t*)(Qb  + kt * 16 + kq + 8);
        aq[kt][3] = *(const uint32_t*)(Qb8 + kt * 16 + kq + 8);
    }

    // ---- scores: 16 MMAs, K B-frags loaded directly from gmem ----
    float S[4][4];
    #pragma unroll
    for (int nt = 0; nt < 4; nt++)
        #pragma unroll
        for (int i = 0; i < 4; i++) S[nt][i] = 0.f;

    int jn = l >> 2;   // n within 8-tile
    #pragma unroll
    for (int nt = 0; nt < 4; nt++) {
        int j = nt * 8 + jn;
        int r = s0 - 16 + j; if (r < 0) r += SLEN;
        const __half* Kb = QKV + (size_t)(r * BSZ + b) * NQKV + EMB + hoff;
        #pragma unroll
        for (int kt = 0; kt < 4; kt++) {
            uint32_t b0 = *(const uint32_t*)(Kb + kt * 16 + kq);
            uint32_t b1 = *(const uint32_t*)(Kb + kt * 16 + kq + 8);
            mma16816(S[nt], aq[kt], b0, b1);
        }
    }

    // ---- mask + scale ----
    int c0 = (l & 3) * 2;
    #pragma unroll
    for (int nt = 0; nt < 4; nt++) {
        #pragma unroll
        for (int i = 0; i < 4; i++) {
            int qi = (i & 2) ? (m0 + 8) : m0;
            int j = nt * 8 + c0 + (i & 1);
            bool valid = (j >= qi + 1) && (j <= qi + 16);
            S[nt][i] = valid ? S[nt][i] * 0.125f : -1e30f;
        }
    }

    // ---- softmax: two rows per lane (m0 via [0,1], m0+8 via [2,3]) ----
    float mxA = -1e30f, mxB = -1e30f;
    #pragma unroll
    for (int nt = 0; nt < 4; nt++) {
        mxA = fmaxf(mxA, fmaxf(S[nt][0], S[nt][1]));
        mxB = fmaxf(mxB, fmaxf(S[nt][2], S[nt][3]));
    }
    #pragma unroll
    for (int o = 1; o <= 2; o <<= 1) {
        mxA = fmaxf(mxA, __shfl_xor_sync(0xffffffffu, mxA, o));
        mxB = fmaxf(mxB, __shfl_xor_sync(0xffffffffu, mxB, o));
    }
    float sA = 0.f, sB2 = 0.f;
    #pragma unroll
    for (int nt = 0; nt < 4; nt++) {
        S[nt][0] = __expf(S[nt][0] - mxA); sA  += S[nt][0];
        S[nt][1] = __expf(S[nt][1] - mxA); sA  += S[nt][1];
        S[nt][2] = __expf(S[nt][2] - mxB); sB2 += S[nt][2];
        S[nt][3] = __expf(S[nt][3] - mxB); sB2 += S[nt][3];
    }
    #pragma unroll
    for (int o = 1; o <= 2; o <<= 1) {
        sA  += __shfl_xor_sync(0xffffffffu, sA,  o);
        sB2 += __shfl_xor_sync(0xffffffffu, sB2, o);
    }
    float invA = 1.0f / sA, invB = 1.0f / sB2;
    #pragma unroll
    for (int nt = 0; nt < 4; nt++) {
        S[nt][0] *= invA; S[nt][1] *= invA;
        S[nt][2] *= invB; S[nt][3] *= invB;
    }

    // ---- pack P into A-fragments (C layout == A layout) ----
    uint32_t pa[2][4];
    #pragma unroll
    for (int kt2 = 0; kt2 < 2; kt2++) {
        __half2 h0 = __floats2half2_rn(S[2*kt2][0],   S[2*kt2][1]);
        __half2 h1 = __floats2half2_rn(S[2*kt2][2],   S[2*kt2][3]);
        __half2 h2 = __floats2half2_rn(S[2*kt2+1][0], S[2*kt2+1][1]);
        __half2 h3 = __floats2half2_rn(S[2*kt2+1][2], S[2*kt2+1][3]);
        pa[kt2][0] = *(uint32_t*)&h0;
        pa[kt2][1] = *(uint32_t*)&h1;
        pa[kt2][2] = *(uint32_t*)&h2;
        pa[kt2][3] = *(uint32_t*)&h3;
    }

    __syncwarp();   // V^T staging visible to ldsm4 (per-warp smem region)

    // ---- O = P @ V : 16 MMAs, B-frags from transposed V in smem ----
    float out[8][4];
    #pragma unroll
    for (int i = 0; i < 8; i++)
        #pragma unroll
        for (int t = 0; t < 4; t++) out[i][t] = 0.f;

    #pragma unroll
    for (int vt16 = 0; vt16 < 4; vt16++) {
        #pragma unroll
        for (int kt2 = 0; kt2 < 2; kt2++) {
            uint32_t br[4];
            ldsm4(br, vtu + (uint32_t)((vt16 * 16 + (l & 15)) * VROWB
                                       + ((l >> 4) << 4) + kt2 * 32));
            mma16816(out[2 * vt16],     pa[kt2], br[0], br[2]);
            mma16816(out[2 * vt16 + 1], pa[kt2], br[1], br[3]);
        }
    }

    // ---- store ----
    __half* O0 = O + (size_t)((s0 + m0)     * BSZ + b) * EMB + hoff;
    __half* O8 = O + (size_t)((s0 + m0 + 8) * BSZ + b) * EMB + hoff;
    #pragma unroll
    for (int nt2 = 0; nt2 < 8; nt2++) {
        int d = nt2 * 8 + c0;
        *(__half2*)(O0 + d) = __floats2half2_rn(out[nt2][0], out[nt2][1]);
        *(__half2*)(O8 + d) = __floats2half2_rn(out[nt2][2], out[nt2][3]);
    }
}

// ---------------- launch ----------------------------------------------------
extern "C" void kernel_launch(void* const* d_in, const int* in_sizes, int n_in,
                              void* d_out, int out_size)
{
    const float* x    = (const float*)d_in[0];
    const float* ln_g = (const float*)d_in[1];
    const float* ln_b = (const float*)d_in[2];
    const float* Wq   = (const float*)d_in[3];
    const float* bq   = (const float*)d_in[4];
    const float* Wk   = (const float*)d_in[5];
    const float* bk   = (const float*)d_in[6];
    const float* Wv   = (const float*)d_in[7];
    const float* bv   = (const float*)d_in[8];
    const float* Wo   = (const float*)d_in[9];
    const float* bo   = (const float*)d_in[10];
    float* out = (float*)d_out;

    __half *xn, *att, *wh, *qkv;
    float *bias;
    cudaGetSymbolAddress((void**)&xn,   g_xn);
    cudaGetSymbolAddress((void**)&att,  g_att);
    cudaGetSymbolAddress((void**)&wh,   g_wh);
    cudaGetSymbolAddress((void**)&qkv,  g_qkv);
    cudaGetSymbolAddress((void**)&bias, g_bias);

    cudaFuncSetAttribute(gemm_mma<1>, cudaFuncAttributeMaxDynamicSharedMemorySize, GEMM_SMEM);
    cudaFuncSetAttribute(gemm_mma<0>, cudaFuncAttributeMaxDynamicSharedMemorySize, GEMM_SMEM);
    cudaFuncSetAttribute(attn_kernel, cudaFuncAttributeMaxDynamicSharedMemorySize, ATTN_SMEM);

    prep_kernel<<<8204, 256>>>(x, ln_g, ln_b, Wq, Wk, Wv, Wo,
                               bq, bk, bv, wh, xn, bias);

    gemm_mma<1><<<dim3(NQKV / GBN, MTOK / GBM), GTHR, GEMM_SMEM>>>(
        xn, wh, bias, nullptr, qkv, NQKV);

    attn_kernel<<<dim3(SLEN / 16, BSZ), 512, ATTN_SMEM>>>(qkv, att);

    gemm_mma<0><<<dim3(EMB / GBN, MTOK / GBM), GTHR, GEMM_SMEM>>>(
        att, wh + (size_t)3 * EMB * EMB, bo, x, out, EMB);
}

// round 14
// speedup vs baseline: 1.2031x; 1.0871x over previous
#include <cuda_runtime.h>
#include <cuda_fp16.h>
#include <cstdint>

#define SLEN 2048
#define BSZ  2
#define EMB  1024
#define NH   16
#define DHD  64
#define PFW  16
#define MTOK (SLEN*BSZ)
#define GBK  32              // K per chunk
#define NCHUNK (EMB/GBK)     // 32
#define GBM  128
#define GBN  256
#define STAGES 4
#define ROWB 80              // padded smem row bytes (64 data + 16 pad)
#define SROWS 384            // A 128 rows + B 256 rows
#define STGB (SROWS*ROWB)    // 30720
#define GEMM_SMEM (STAGES*STGB)  // 122880
#define GTHR 512
#define NQKV 3072
#define KROWB 144            // attn K/V smem row pitch (128 data + 16 pad)
#define KV_BYTES (2*32*KROWB)    // 9216 per warp (K 32 rows + V 32 rows)
#define ATTN_SMEM (16*KV_BYTES)  // 147456

// ---------------- scratch (static device arrays; no allocation) -------------
__device__ __align__(16) __half g_xn [MTOK*EMB];        // LN out fp16
__device__ __align__(16) __half g_att[MTOK*EMB];        // attn out fp16
__device__ __align__(16) __half g_wh [4*EMB*EMB];       // Wq|Wk|Wv|Wo fp16, [N][K]
__device__ __align__(16) __half g_qkv[MTOK*NQKV];       // fused QKV output (fp16)
__device__ float g_bias[NQKV];

// ---------------- PTX helpers ------------------------------------------------
__device__ __forceinline__ uint32_t s2u(const void* p) {
    uint32_t a;
    asm("{ .reg .u64 t; cvta.to.shared.u64 t, %1; cvt.u32.u64 %0, t; }" : "=r"(a) : "l"(p));
    return a;
}
__device__ __forceinline__ void cp16(uint32_t dst, const void* src) {
    asm volatile("cp.async.cg.shared.global [%0], [%1], 16;" :: "r"(dst), "l"(src));
}
#define CP_COMMIT() asm volatile("cp.async.commit_group;" ::: "memory")

__device__ __forceinline__ void ldsm4(uint32_t* r, uint32_t addr) {
    asm volatile("ldmatrix.sync.aligned.m8n8.x4.shared.b16 {%0,%1,%2,%3}, [%4];"
        : "=r"(r[0]), "=r"(r[1]), "=r"(r[2]), "=r"(r[3]) : "r"(addr));
}
__device__ __forceinline__ void ldsm4t(uint32_t* r, uint32_t addr) {
    asm volatile("ldmatrix.sync.aligned.m8n8.x4.trans.shared.b16 {%0,%1,%2,%3}, [%4];"
        : "=r"(r[0]), "=r"(r[1]), "=r"(r[2]), "=r"(r[3]) : "r"(addr));
}
__device__ __forceinline__ void mma16816(float* d, const uint32_t* a,
                                         uint32_t b0, uint32_t b1) {
    asm volatile("mma.sync.aligned.m16n8k16.row.col.f32.f16.f16.f32 "
        "{%0,%1,%2,%3}, {%4,%5,%6,%7}, {%8,%9}, {%0,%1,%2,%3};"
        : "+f"(d[0]), "+f"(d[1]), "+f"(d[2]), "+f"(d[3])
        : "r"(a[0]), "r"(a[1]), "r"(a[2]), "r"(a[3]), "r"(b0), "r"(b1));
}

// ---------------- merged prep: wprep (blocks 0..4095) + LN (4096..8191)
//                  + bias concat (8192..8203), one launch --------------------
__global__ void __launch_bounds__(256) prep_kernel(
    const float* __restrict__ x,
    const float* __restrict__ gamma,
    const float* __restrict__ beta,
    const float* __restrict__ W0, const float* __restrict__ W1,
    const float* __restrict__ W2, const float* __restrict__ W3,
    const float* __restrict__ bq, const float* __restrict__ bk,
    const float* __restrict__ bv,
    __half* __restrict__ Bh,
    __half* __restrict__ xn,
    float* __restrict__ bqkv)
{
    int bid = blockIdx.x;
    int tid = threadIdx.x;

    if (bid < 4096) {
        int wsel = bid >> 10;
        int t = bid & 1023;
        int n0 = (t & 31) * 32;
        int k0 = (t >> 5) * 32;
        const float* W = (wsel == 0) ? W0 : (wsel == 1) ? W1
                       : (wsel == 2) ? W2 : W3;
        __half* B = Bh + (size_t)wsel * EMB * EMB;
        __shared__ float tile[32][33];
        int tx = tid & 31;
        int ty = tid >> 5;
        #pragma unroll
        for (int r = ty; r < 32; r += 8)
            tile[r][tx] = W[(size_t)(k0 + r) * EMB + n0 + tx];
        __syncthreads();
        #pragma unroll
        for (int r = ty; r < 32; r += 8)
            B[(size_t)(n0 + r) * EMB + (k0 + tx)] = __float2half(tile[tx][r]);
    } else if (bid < 8192) {
        int row = bid - 4096;
        const float4 xv = ((const float4*)(x + (size_t)row * EMB))[tid];
        float s  = xv.x + xv.y + xv.z + xv.w;
        float s2 = xv.x*xv.x + xv.y*xv.y + xv.z*xv.z + xv.w*xv.w;
        #pragma unroll
        for (int o = 16; o > 0; o >>= 1) {
            s  += __shfl_xor_sync(0xffffffffu, s,  o);
            s2 += __shfl_xor_sync(0xffffffffu, s2, o);
        }
        __shared__ float rs[8], rs2[8];
        __shared__ float mean_s, rstd_s;
        int w = tid >> 5, l = tid & 31;
        if (l == 0) { rs[w] = s; rs2[w] = s2; }
        __syncthreads();
        if (tid == 0) {
            float ts = 0.f, ts2 = 0.f;
            #pragma unroll
            for (int i = 0; i < 8; i++) { ts += rs[i]; ts2 += rs2[i]; }
            float mean = ts * (1.0f / EMB);
            float var  = ts2 * (1.0f / EMB) - mean * mean;
            mean_s = mean;
            rstd_s = rsqrtf(var + 1e-5f);
        }
        __syncthreads();
        float mean = mean_s, r = rstd_s;
        float4 gv = ((const float4*)gamma)[tid];
        float4 bv2 = ((const float4*)beta)[tid];
        __half h[4];
        h[0] = __float2half((xv.x - mean) * r * gv.x + bv2.x);
        h[1] = __float2half((xv.y - mean) * r * gv.y + bv2.y);
        h[2] = __float2half((xv.z - mean) * r * gv.z + bv2.z);
        h[3] = __float2half((xv.w - mean) * r * gv.w + bv2.w);
        *(uint2*)(xn + (size_t)row * EMB + tid * 4) = *(uint2*)h;
    } else {
        int i = (bid - 8192) * 256 + tid;
        if (i < NQKV)
            bqkv[i] = (i < EMB) ? bq[i] : (i < 2*EMB) ? bk[i - EMB] : bv[i - 2*EMB];
    }
}

// ---------------- HMMA fp16 GEMM: C = A @ B^T + bias (+res) ----------------
template<int OUT_HALF>
__global__ void __launch_bounds__(GTHR, 1) gemm_mma(
    const __half* __restrict__ A,
    const __half* __restrict__ B,
    const float* __restrict__ bias,
    const float* __restrict__ res,
    void* __restrict__ Cv,
    int ldc)
{
    extern __shared__ char smem[];
    uint32_t sb = s2u(smem);
    int tid = threadIdx.x;
    int w = tid >> 5, l = tid & 31;
    int bm = blockIdx.y * GBM;
    int bn = blockIdx.x * GBN;
    int wm = (w & 3) * 32;
    int wn = (w >> 2) * 64;

    int r0 = tid >> 2;
    int ch = tid & 3;
    const __half* p0 = A + (size_t)(bm + r0) * EMB + ch * 8;
    const __half* p1 = B + (size_t)(bn + r0) * EMB + ch * 8;
    const __half* p2 = B + (size_t)(bn + r0 + 128) * EMB + ch * 8;
    uint32_t d0 = (uint32_t)r0 * ROWB + ch * 16;
    uint32_t d1 = d0 + 128 * ROWB;
    uint32_t d2 = d0 + 256 * ROWB;

    float acc[2][8][4];
    #pragma unroll
    for (int i = 0; i < 2; i++)
        #pragma unroll
        for (int j = 0; j < 8; j++)
            #pragma unroll
            for (int t = 0; t < 4; t++) acc[i][j][t] = 0.f;

    #pragma unroll
    for (int c = 0; c < STAGES - 1; c++) {
        uint32_t stg = sb + c * STGB;
        cp16(stg + d0, p0); p0 += GBK;
        cp16(stg + d1, p1); p1 += GBK;
        cp16(stg + d2, p2); p2 += GBK;
        CP_COMMIT();
    }

    uint32_t arow = (uint32_t)(wm + (l & 15)) * ROWB + ((l >> 4) << 4);
    uint32_t brow = (uint32_t)(128 + wn + (l & 15)) * ROWB + ((l >> 4) << 4);

    for (int c0 = 0; c0 < NCHUNK; c0 += STAGES) {
        #pragma unroll
        for (int s = 0; s < STAGES; s++) {
            int c = c0 + s;
            asm volatile("cp.async.wait_group %0;" :: "n"(STAGES - 2) : "memory");
            __syncthreads();
            uint32_t stg = sb + (uint32_t)s * STGB;

            if (c + STAGES - 1 < NCHUNK) {
                uint32_t ds = sb + (uint32_t)(((unsigned)(s + STAGES - 1)) & (STAGES - 1)) * STGB;
                cp16(ds + d0, p0); p0 += GBK;
                cp16(ds + d1, p1); p1 += GBK;
                cp16(ds + d2, p2); p2 += GBK;
            }
            CP_COMMIT();

            uint32_t sA = stg + arow;
            uint32_t sB = stg + brow;

            #pragma unroll
            for (int ks = 0; ks < 2; ks++) {
                uint32_t af[2][4], br[4][4];
                #pragma unroll
                for (int mt = 0; mt < 2; mt++)
                    ldsm4(af[mt], sA + mt * (16 * ROWB) + ks * 32);
                #pragma unroll
                for (int bt = 0; bt < 4; bt++)
                    ldsm4(br[bt], sB + bt * (16 * ROWB) + ks * 32);
                #pragma unroll
                for (int mt = 0; mt < 2; mt++)
                    #pragma unroll
                    for (int bt = 0; bt < 4; bt++) {
                        mma16816(acc[mt][2 * bt],     af[mt], br[bt][0], br[bt][2]);
                        mma16816(acc[mt][2 * bt + 1], af[mt], br[bt][1], br[bt][3]);
                    }
            }
        }
    }

    int rbase = bm + wm + (l >> 2);
    int cbase = bn + wn + 2 * (l & 3);
    #pragma unroll
    for (int mt = 0; mt < 2; mt++) {
        #pragma unroll
        for (int nt = 0; nt < 8; nt++) {
            int col = cbase + nt * 8;
            float bx = bias[col], by = bias[col + 1];
            int rr0 = rbase + mt * 16;
            int rr1 = rr0 + 8;
            float v0x = acc[mt][nt][0] + bx;
            float v0y = acc[mt][nt][1] + by;
            float v1x = acc[mt][nt][2] + bx;
            float v1y = acc[mt][nt][3] + by;
            if (OUT_HALF) {
                __half* C = (__half*)Cv;
                *(__half2*)(C + (size_t)rr0 * ldc + col) = __floats2half2_rn(v0x, v0y);
                *(__half2*)(C + (size_t)rr1 * ldc + col) = __floats2half2_rn(v1x, v1y);
            } else {
                float* C = (float*)Cv;
                float2 q0 = *(const float2*)(res + (size_t)rr0 * EMB + col);
                float2 q1 = *(const float2*)(res + (size_t)rr1 * EMB + col);
                float2 o0 = {v0x + q0.x, v0y + q0.y};
                float2 o1 = {v1x + q1.x, v1y + q1.y};
                *(float2*)(C + (size_t)rr0 * ldc + col) = o0;
                *(float2*)(C + (size_t)rr1 * ldc + col) = o1;
            }
        }
    }
}

// ---------------- tensor-core sliding-window attention v3 -------------------
// One warp = (16-query block, head, b). K and V windows (32 rows x 128 B)
// staged via cp.async into per-warp smem. Score B-frags via non-trans ldsm4
// (GEMM-validated pattern); P.V B-frags via ldsm4.trans on row-major V.
__global__ void __launch_bounds__(512) attn_kernel(
    const __half* __restrict__ QKV,
    __half* __restrict__ O)
{
    extern __shared__ char smem[];
    int w = threadIdx.x >> 5, l = threadIdx.x & 31;
    uint32_t ku = s2u(smem) + w * KV_BYTES;          // K rows 0..31
    uint32_t vu = ku + 32 * KROWB;                   // V rows 0..31
    int s0 = blockIdx.x * 16;
    int b = blockIdx.y;
    int hoff = w * DHD;          // warp = head
    int m0 = l >> 2;             // owned rows: m0 and m0+8
    int kq = (l & 3) * 2;

    // ---- stage K then V rows via cp.async (lane l owns window row l) ----
    {
        int r = s0 - 16 + l; if (r < 0) r += SLEN;
        const __half* Krow = QKV + (size_t)(r * BSZ + b) * NQKV + EMB + hoff;
        const __half* Vrow = QKV + (size_t)(r * BSZ + b) * NQKV + 2 * EMB + hoff;
        #pragma unroll
        for (int i = 0; i < 8; i++)
            cp16(ku + (uint32_t)l * KROWB + i * 16, Krow + i * 8);
        CP_COMMIT();
        #pragma unroll
        for (int i = 0; i < 8; i++)
            cp16(vu + (uint32_t)l * KROWB + i * 16, Vrow + i * 8);
        CP_COMMIT();
    }

    // ---- Q A-fragments (direct gmem loads; overlaps staging) ----
    const __half* Qb  = QKV + (size_t)((s0 + m0)     * BSZ + b) * NQKV + hoff;
    const __half* Qb8 = QKV + (size_t)((s0 + m0 + 8) * BSZ + b) * NQKV + hoff;
    uint32_t aq[4][4];
    #pragma unroll
    for (int kt = 0; kt < 4; kt++) {
        aq[kt][0] = *(const uint32_t*)(Qb  + kt * 16 + kq);
        aq[kt][1] = *(const uint32_t*)(Qb8 + kt * 16 + kq);
        aq[kt][2] = *(const uint32_t*)(Qb  + kt * 16 + kq + 8);
        aq[kt][3] = *(const uint32_t*)(Qb8 + kt * 16 + kq + 8);
    }

    // K staged (group 1 = V still allowed in flight)
    asm volatile("cp.async.wait_group 1;" ::: "memory");
    __syncwarp();

    // ---- scores: S[nt] = j-tile nt*8..+7; ldsm4 like GEMM B ----
    float S[4][4];
    #pragma unroll
    for (int nt = 0; nt < 4; nt++)
        #pragma unroll
        for (int i = 0; i < 4; i++) S[nt][i] = 0.f;

    uint32_t kbase = ku + (uint32_t)(l & 15) * KROWB + ((l >> 4) << 4);
    #pragma unroll
    for (int kt = 0; kt < 4; kt++) {
        uint32_t br0[4], br1[4];
        ldsm4(br0, kbase + kt * 32);                    // j rows 0..15
        ldsm4(br1, kbase + 16 * KROWB + kt * 32);       // j rows 16..31
        mma16816(S[0], aq[kt], br0[0], br0[2]);
        mma16816(S[1], aq[kt], br0[1], br0[3]);
        mma16816(S[2], aq[kt], br1[0], br1[2]);
        mma16816(S[3], aq[kt], br1[1], br1[3]);
    }

    // ---- mask + scale ----
    int c0 = (l & 3) * 2;
    #pragma unroll
    for (int nt = 0; nt < 4; nt++) {
        #pragma unroll
        for (int i = 0; i < 4; i++) {
            int qi = (i & 2) ? (m0 + 8) : m0;
            int j = nt * 8 + c0 + (i & 1);
            bool valid = (j >= qi + 1) && (j <= qi + 16);
            S[nt][i] = valid ? S[nt][i] * 0.125f : -1e30f;
        }
    }

    // ---- softmax: two rows per lane ----
    float mxA = -1e30f, mxB = -1e30f;
    #pragma unroll
    for (int nt = 0; nt < 4; nt++) {
        mxA = fmaxf(mxA, fmaxf(S[nt][0], S[nt][1]));
        mxB = fmaxf(mxB, fmaxf(S[nt][2], S[nt][3]));
    }
    #pragma unroll
    for (int o = 1; o <= 2; o <<= 1) {
        mxA = fmaxf(mxA, __shfl_xor_sync(0xffffffffu, mxA, o));
        mxB = fmaxf(mxB, __shfl_xor_sync(0xffffffffu, mxB, o));
    }
    float sA = 0.f, sB2 = 0.f;
    #pragma unroll
    for (int nt = 0; nt < 4; nt++) {
        S[nt][0] = __expf(S[nt][0] - mxA); sA  += S[nt][0];
        S[nt][1] = __expf(S[nt][1] - mxA); sA  += S[nt][1];
        S[nt][2] = __expf(S[nt][2] - mxB); sB2 += S[nt][2];
        S[nt][3] = __expf(S[nt][3] - mxB); sB2 += S[nt][3];
    }
    #pragma unroll
    for (int o = 1; o <= 2; o <<= 1) {
        sA  += __shfl_xor_sync(0xffffffffu, sA,  o);
        sB2 += __shfl_xor_sync(0xffffffffu, sB2, o);
    }
    float invA = 1.0f / sA, invB = 1.0f / sB2;
    #pragma unroll
    for (int nt = 0; nt < 4; nt++) {
        S[nt][0] *= invA; S[nt][1] *= invA;
        S[nt][2] *= invB; S[nt][3] *= invB;
    }

    // ---- pack P into A-fragments (C layout == A layout) ----
    uint32_t pa[2][4];
    #pragma unroll
    for (int kt2 = 0; kt2 < 2; kt2++) {
        __half2 h0 = __floats2half2_rn(S[2*kt2][0],   S[2*kt2][1]);
        __half2 h1 = __floats2half2_rn(S[2*kt2][2],   S[2*kt2][3]);
        __half2 h2 = __floats2half2_rn(S[2*kt2+1][0], S[2*kt2+1][1]);
        __half2 h3 = __floats2half2_rn(S[2*kt2+1][2], S[2*kt2+1][3]);
        pa[kt2][0] = *(uint32_t*)&h0;
        pa[kt2][1] = *(uint32_t*)&h1;
        pa[kt2][2] = *(uint32_t*)&h2;
        pa[kt2][3] = *(uint32_t*)&h3;
    }

    // V staged
    asm volatile("cp.async.wait_group 0;" ::: "memory");
    __syncwarp();

    // ---- O = P @ V : B-frags via ldsm4.trans on row-major V ----
    // lane addr: row = kt*16 + ((l&16)>>1) + (l&7); col = ng*16 + (l&8)
    float out[8][4];
    #pragma unroll
    for (int i = 0; i < 8; i++)
        #pragma unroll
        for (int t = 0; t < 4; t++) out[i][t] = 0.f;

    uint32_t vlane = vu + (uint32_t)(((l & 16) >> 1) + (l & 7)) * KROWB
                        + (uint32_t)(l & 8) * 2;
    #pragma unroll
    for (int kt2 = 0; kt2 < 2; kt2++) {
        #pragma unroll
        for (int ng = 0; ng < 4; ng++) {
            uint32_t br[4];
            ldsm4t(br, vlane + kt2 * (16 * KROWB) + ng * 32);
            mma16816(out[2 * ng],     pa[kt2], br[0], br[2]);
            mma16816(out[2 * ng + 1], pa[kt2], br[1], br[3]);
        }
    }

    // ---- store ----
    __half* O0 = O + (size_t)((s0 + m0)     * BSZ + b) * EMB + hoff;
    __half* O8 = O + (size_t)((s0 + m0 + 8) * BSZ + b) * EMB + hoff;
    #pragma unroll
    for (int nt2 = 0; nt2 < 8; nt2++) {
        int d = nt2 * 8 + c0;
        *(__half2*)(O0 + d) = __floats2half2_rn(out[nt2][0], out[nt2][1]);
        *(__half2*)(O8 + d) = __floats2half2_rn(out[nt2][2], out[nt2][3]);
    }
}

// ---------------- launch ----------------------------------------------------
extern "C" void kernel_launch(void* const* d_in, const int* in_sizes, int n_in,
                              void* d_out, int out_size)
{
    const float* x    = (const float*)d_in[0];
    const float* ln_g = (const float*)d_in[1];
    const float* ln_b = (const float*)d_in[2];
    const float* Wq   = (const float*)d_in[3];
    const float* bq   = (const float*)d_in[4];
    const float* Wk   = (const float*)d_in[5];
    const float* bk   = (const float*)d_in[6];
    const float* Wv   = (const float*)d_in[7];
    const float* bv   = (const float*)d_in[8];
    const float* Wo   = (const float*)d_in[9];
    const float* bo   = (const float*)d_in[10];
    float* out = (float*)d_out;

    __half *xn, *att, *wh, *qkv;
    float *bias;
    cudaGetSymbolAddress((void**)&xn,   g_xn);
    cudaGetSymbolAddress((void**)&att,  g_att);
    cudaGetSymbolAddress((void**)&wh,   g_wh);
    cudaGetSymbolAddress((void**)&qkv,  g_qkv);
    cudaGetSymbolAddress((void**)&bias, g_bias);

    cudaFuncSetAttribute(gemm_mma<1>, cudaFuncAttributeMaxDynamicSharedMemorySize, GEMM_SMEM);
    cudaFuncSetAttribute(gemm_mma<0>, cudaFuncAttributeMaxDynamicSharedMemorySize, GEMM_SMEM);
    cudaFuncSetAttribute(attn_kernel, cudaFuncAttributeMaxDynamicSharedMemorySize, ATTN_SMEM);

    prep_kernel<<<8204, 256>>>(x, ln_g, ln_b, Wq, Wk, Wv, Wo,
                               bq, bk, bv, wh, xn, bias);

    gemm_mma<1><<<dim3(NQKV / GBN, MTOK / GBM), GTHR, GEMM_SMEM>>>(
        xn, wh, bias, nullptr, qkv, NQKV);

    attn_kernel<<<dim3(SLEN / 16, BSZ), 512, ATTN_SMEM>>>(qkv, att);

    gemm_mma<0><<<dim3(EMB / GBN, MTOK / GBM), GTHR, GEMM_SMEM>>>(
        att, wh + (size_t)3 * EMB * EMB, bo, x, out, EMB);
}